// round 12
// baseline (speedup 1.0000x reference)
#include <cuda_runtime.h>

// Uniform cubic B-spline via per-interval monomial (Horner) form.
// t = (x+1)*31.5 in [0,63], j = trunc(t), u = t-j,
// out = p0[j] + u*(p1[j] + u*(p2[j] + u*p3[j])), with
//   p0=(c0+4c1+c2)/6, p1=(c2-c0)/2, p2=(c0-2c1+c2)/2, p3=(c3-c0+3(c1-c2))/6.
// Table padded to 64 entries (entry 63 dups interval 62) -> no clamp in loop.
// Shared table replicated 8x across the eight 16B bank groups: every LDS.128
// quarter-warp phase is conflict-free for random j.
//
// R12: lane-interleaved MLP=4 with a real register budget.
// __launch_bounds__(512,3) -> 42 regs/thread, 48 warps/SM, grid 444 = one
// exact wave. 4 independent fully-coalesced float4 streams per iteration.
// (R4 ran MLP=4 at 32 regs -> serialized; R7 ran it with the bad contiguous-
// pair layout. This is the clean cell.)

#define REP  8
#define NTBL 64

__device__ __forceinline__ float eval_one(float x, const float4* __restrict__ tp) {
    float t = fmaf(x, 31.5f, 31.5f);     // in [0, 63]
    int j = (int)t;                      // trunc == floor; 0..63 (padded table)
    float u = t - (float)j;
    float4 p = tp[j * REP];              // tp pre-offset by lane's bank-group
    return fmaf(fmaf(fmaf(p.w, u, p.z), u, p.y), u, p.x);
}

__device__ __forceinline__ float4 eval_four(float4 xv, const float4* __restrict__ tp) {
    float4 ov;
    ov.x = eval_one(xv.x, tp);
    ov.y = eval_one(xv.y, tp);
    ov.z = eval_one(xv.z, tp);
    ov.w = eval_one(xv.w, tp);
    return ov;
}

__global__ void __launch_bounds__(512, 3)
bspline_kernel(const float4* __restrict__ x4,
               const float* __restrict__ coeffs,
               float4* __restrict__ o4, int n4) {
    __shared__ float4 tbl[NTBL * REP];
    int tid = threadIdx.x;
    // 512 entries / 512 threads: one entry each.
    {
        int j = min(tid >> 3, 62);       // entry 63 duplicates interval 62
        float c0 = __ldg(coeffs + j);
        float c1 = __ldg(coeffs + j + 1);
        float c2 = __ldg(coeffs + j + 2);
        float c3 = __ldg(coeffs + j + 3);
        float4 p;
        p.x = fmaf(4.0f, c1, c0 + c2) * 0.16666666666666666f;
        p.y = (c2 - c0) * 0.5f;
        p.z = fmaf(-2.0f, c1, c0 + c2) * 0.5f;
        p.w = fmaf(3.0f, c1 - c2, c3 - c0) * 0.16666666666666666f;
        tbl[tid] = p;
    }
    __syncthreads();

    const float4* __restrict__ tp = tbl + (tid & (REP - 1));
    const int stride = gridDim.x * blockDim.x;
    int i = blockIdx.x * blockDim.x + tid;

    // Lane-interleaved MLP=4: four independent, fully-coalesced streams.
    for (; i + 3 * stride < n4; i += 4 * stride) {
        float4 xa = x4[i];
        float4 xb = x4[i + stride];
        float4 xc = x4[i + 2 * stride];
        float4 xd = x4[i + 3 * stride];
        o4[i]              = eval_four(xa, tp);
        o4[i + stride]     = eval_four(xb, tp);
        o4[i + 2 * stride] = eval_four(xc, tp);
        o4[i + 3 * stride] = eval_four(xd, tp);
    }
    // MLP=2 tail
    if (i + stride < n4) {
        float4 xa = x4[i];
        float4 xb = x4[i + stride];
        o4[i]          = eval_four(xa, tp);
        o4[i + stride] = eval_four(xb, tp);
        i += 2 * stride;
    }
    // scalar tail
    if (i < n4) {
        float4 xa = x4[i];
        o4[i] = eval_four(xa, tp);
    }
}

extern "C" void kernel_launch(void* const* d_in, const int* in_sizes, int n_in,
                              void* d_out, int out_size) {
    const float* x      = (const float*)d_in[0];
    const float* coeffs = (const float*)d_in[1];
    float* out = (float*)d_out;
    int n  = in_sizes[0];
    int n4 = n >> 2;                 // N = 2^22, divisible by 4
    int threads = 512;
    int blocks  = 444;               // 3 CTAs/SM x 148 SMs = one exact wave
    int max_blocks = (n4 + threads - 1) / threads;
    if (blocks > max_blocks) blocks = max_blocks;
    if (blocks < 1) blocks = 1;
    bspline_kernel<<<blocks, threads>>>((const float4*)x, coeffs, (float4*)out, n4);
}

// round 13
// speedup vs baseline: 1.2574x; 1.2574x over previous
#include <cuda_runtime.h>
#include <cstdint>

// Uniform cubic B-spline via per-interval monomial (Horner) form.
// t = (x+1)*31.5 in [0,63], j = trunc(t), u = t-j,
// out = p0[j] + u*(p1[j] + u*(p2[j] + u*p3[j])).
// Table padded to 64 entries; 8-way bank-group replication -> conflict-free
// LDS.128 gathers.
//
// R13: x arrives via cp.async.bulk (TMA 1D) into double-buffered shared
// memory. No per-warp global-load scoreboard stalls in the main loop:
// wait mbarrier once per 8KB chunk, then pure LDS -> Horner -> STG.
// 1024 CTAs x 512 threads, 16KB slice per CTA (exact for N = 2^22).

#define REP   8
#define NTBL  64
#define CHUNK 512                    // float4 per chunk (8KB)

__device__ __forceinline__ uint32_t smem_u32(const void* p) {
    return (uint32_t)__cvta_generic_to_shared(p);
}

__device__ __forceinline__ void mbar_init(uint32_t mbar, uint32_t count) {
    asm volatile("mbarrier.init.shared.b64 [%0], %1;" :: "r"(mbar), "r"(count) : "memory");
}
__device__ __forceinline__ void mbar_expect_tx(uint32_t mbar, uint32_t bytes) {
    asm volatile("mbarrier.arrive.expect_tx.shared.b64 _, [%0], %1;"
                 :: "r"(mbar), "r"(bytes) : "memory");
}
__device__ __forceinline__ void bulk_g2s(uint32_t dst, const void* src,
                                         uint32_t bytes, uint32_t mbar) {
    asm volatile("cp.async.bulk.shared::cta.global.mbarrier::complete_tx::bytes "
                 "[%0], [%1], %2, [%3];"
                 :: "r"(dst), "l"(src), "r"(bytes), "r"(mbar) : "memory");
}
__device__ __forceinline__ void mbar_wait(uint32_t mbar, uint32_t parity) {
    asm volatile(
        "{\n\t"
        ".reg .pred P;\n\t"
        "WAIT_%=: \n\t"
        "mbarrier.try_wait.parity.acquire.cta.shared::cta.b64 P, [%0], %1, 0x989680;\n\t"
        "@P bra.uni DONE_%=;\n\t"
        "bra.uni WAIT_%=;\n\t"
        "DONE_%=: \n\t"
        "}"
        :: "r"(mbar), "r"(parity) : "memory");
}

__device__ __forceinline__ float eval_one(float x, const float4* __restrict__ tp) {
    float t = fmaf(x, 31.5f, 31.5f);     // in [0, 63]
    int j = (int)t;                      // trunc == floor; table padded to 64
    float u = t - (float)j;
    float4 p = tp[j * REP];              // tp pre-offset by lane's bank-group
    return fmaf(fmaf(fmaf(p.w, u, p.z), u, p.y), u, p.x);
}

__device__ __forceinline__ float4 eval_four(float4 xv, const float4* __restrict__ tp) {
    float4 ov;
    ov.x = eval_one(xv.x, tp);
    ov.y = eval_one(xv.y, tp);
    ov.z = eval_one(xv.z, tp);
    ov.w = eval_one(xv.w, tp);
    return ov;
}

__global__ void __launch_bounds__(512, 4)
bspline_kernel(const float4* __restrict__ x4,
               const float* __restrict__ coeffs,
               float4* __restrict__ o4, int n4) {
    __shared__ float4 tbl[NTBL * REP];               // 8 KB
    __shared__ float4 xbuf[2][CHUNK];                // 16 KB
    __shared__ __align__(8) unsigned long long mbar_s[2];
    int tid = threadIdx.x;

    // Table build: one entry per thread.
    {
        int j = min(tid >> 3, 62);       // entry 63 duplicates interval 62
        float c0 = __ldg(coeffs + j);
        float c1 = __ldg(coeffs + j + 1);
        float c2 = __ldg(coeffs + j + 2);
        float c3 = __ldg(coeffs + j + 3);
        float4 p;
        p.x = fmaf(4.0f, c1, c0 + c2) * 0.16666666666666666f;
        p.y = (c2 - c0) * 0.5f;
        p.z = fmaf(-2.0f, c1, c0 + c2) * 0.5f;
        p.w = fmaf(3.0f, c1 - c2, c3 - c0) * 0.16666666666666666f;
        tbl[tid] = p;
    }

    int base = blockIdx.x * (2 * CHUNK);             // float4 index of slice
    int rem  = n4 - base;
    if (rem <= 0) return;                            // (not hit for N=2^22)
    int cnt0 = min(rem, CHUNK);
    int cnt1 = min(max(rem - CHUNK, 0), CHUNK);

    uint32_t mb0 = smem_u32(&mbar_s[0]);
    uint32_t mb1 = smem_u32(&mbar_s[1]);
    if (tid == 0) {
        mbar_init(mb0, 1);
        mbar_init(mb1, 1);
    }
    __syncthreads();                                 // init visible before TMA

    if (tid == 0) {
        mbar_expect_tx(mb0, (uint32_t)cnt0 * 16u);
        bulk_g2s(smem_u32(&xbuf[0][0]), x4 + base, (uint32_t)cnt0 * 16u, mb0);
        if (cnt1 > 0) {
            mbar_expect_tx(mb1, (uint32_t)cnt1 * 16u);
            bulk_g2s(smem_u32(&xbuf[1][0]), x4 + base + CHUNK,
                     (uint32_t)cnt1 * 16u, mb1);
        }
    }

    const float4* __restrict__ tp = tbl + (tid & (REP - 1));

    // Chunk 0
    mbar_wait(mb0, 0);
    if (tid < cnt0) {
        float4 xv = xbuf[0][tid];
        o4[base + tid] = eval_four(xv, tp);
    }
    // Chunk 1
    if (cnt1 > 0) {
        mbar_wait(mb1, 0);
        if (tid < cnt1) {
            float4 xv = xbuf[1][tid];
            o4[base + CHUNK + tid] = eval_four(xv, tp);
        }
    }
}

extern "C" void kernel_launch(void* const* d_in, const int* in_sizes, int n_in,
                              void* d_out, int out_size) {
    const float* x      = (const float*)d_in[0];
    const float* coeffs = (const float*)d_in[1];
    float* out = (float*)d_out;
    int n  = in_sizes[0];
    int n4 = n >> 2;                           // N = 2^22 -> n4 = 2^20
    int threads = 512;
    int blocks  = (n4 + 2 * CHUNK - 1) / (2 * CHUNK);   // 1024 for N=2^22
    if (blocks < 1) blocks = 1;
    bspline_kernel<<<blocks, threads>>>((const float4*)x, coeffs, (float4*)out, n4);
}